// round 1
// baseline (speedup 1.0000x reference)
#include <cuda_runtime.h>
#include <math_constants.h>

#define B_ 8
#define C_ 128
#define H_ 48
#define W_ 48
#define N_ (H_*W_)   // 2304
#define NTILES (N_/64) // 36

// Scratch (device globals: allocation-free per harness rules)
__device__ float g_q[B_*C_*N_];
__device__ float g_k[B_*C_*N_];
__device__ float g_v[B_*C_*N_];
__device__ float g_o[B_*C_*N_];
__device__ float g_se[B_*C_];

// ---------------------------------------------------------------------------
// QKV projection: out[b][o][n] = sum_c W[o][c] * x[b][c][n] + bias[o]
// grid: (N/64, C/64, 3*B), block 256, 64x64 tile, K-tiles of 32
// ---------------------------------------------------------------------------
__global__ __launch_bounds__(256) void qkv_kernel(
    const float* __restrict__ x,
    const float* __restrict__ Wq, const float* __restrict__ bq,
    const float* __restrict__ Wk, const float* __restrict__ bk,
    const float* __restrict__ Wv, const float* __restrict__ bv)
{
    int b = blockIdx.z & 7;
    int which = blockIdx.z >> 3;
    const float* Wm   = (which == 0) ? Wq : (which == 1) ? Wk : Wv;
    const float* bias = (which == 0) ? bq : (which == 1) ? bk : bv;
    float* dst        = (which == 0) ? g_q : (which == 1) ? g_k : g_v;

    int o0 = blockIdx.y * 64;
    int n0 = blockIdx.x * 64;

    __shared__ float Ws[64][33];
    __shared__ float Xs[32][64];

    int tid = threadIdx.x;
    int ty = tid >> 4, tx = tid & 15;

    float acc[4][4] = {};
    const float* xb = x + (size_t)b * C_ * N_;

    for (int k0 = 0; k0 < C_; k0 += 32) {
        for (int t = tid; t < 64*32; t += 256) {
            int oo = t >> 5, kk = t & 31;
            Ws[oo][kk] = Wm[(o0 + oo) * C_ + k0 + kk];
        }
        for (int t = tid; t < 32*64; t += 256) {
            int kk = t >> 6, nn = t & 63;
            Xs[kk][nn] = xb[(size_t)(k0 + kk) * N_ + n0 + nn];
        }
        __syncthreads();
        #pragma unroll
        for (int kk = 0; kk < 32; kk++) {
            float a[4], bb[4];
            #pragma unroll
            for (int r = 0; r < 4; r++) a[r] = Ws[ty*4 + r][kk];
            #pragma unroll
            for (int j = 0; j < 4; j++) bb[j] = Xs[kk][tx*4 + j];
            #pragma unroll
            for (int r = 0; r < 4; r++)
                #pragma unroll
                for (int j = 0; j < 4; j++)
                    acc[r][j] += a[r] * bb[j];
        }
        __syncthreads();
    }

    #pragma unroll
    for (int r = 0; r < 4; r++) {
        int o = o0 + ty*4 + r;
        float bv_ = bias[o];
        #pragma unroll
        for (int j = 0; j < 4; j++) {
            dst[((size_t)b * C_ + o) * N_ + n0 + tx*4 + j] = acc[r][j] + bv_;
        }
    }
}

// ---------------------------------------------------------------------------
// Flash attention: S = Q^T K (no scale), softmax over j, O = P * V^T
// grid: (N/64, B), block 256. BM=BN=64, d=C=128.
// Thread layout 16x16; S frag 4x4 (rows ty*4.., cols tx*4..);
// O frag 4x8 (rows ty*4.., channels tx*8..). P staged through shared.
// ---------------------------------------------------------------------------
#define QS_OFF 0
#define KS_OFF (64*129)
#define VS_OFF (2*64*129)
#define PS_OFF (3*64*129)
#define ATTN_SMEM_FLOATS (3*64*129 + 64*65)

__global__ __launch_bounds__(256) void attn_kernel()
{
    extern __shared__ float sm[];
    float* Qs = sm + QS_OFF;   // [64][129]
    float* Ks = sm + KS_OFF;   // [64][129]
    float* Vs = sm + VS_OFF;   // [64][129]
    float* Ps = sm + PS_OFF;   // [64][65]

    int b  = blockIdx.y;
    int i0 = blockIdx.x * 64;
    int tid = threadIdx.x;
    int ty = tid >> 4, tx = tid & 15;

    // Load Q tile transposed: Qs[i][c] = q[b][c][i0+i]
    for (int t = tid; t < 128*64; t += 256) {
        int c = t >> 6, ii = t & 63;
        Qs[ii*129 + c] = g_q[((size_t)b * C_ + c) * N_ + i0 + ii];
    }

    float m[4], l[4], O[4][8];
    #pragma unroll
    for (int r = 0; r < 4; r++) {
        m[r] = -CUDART_INF_F; l[r] = 0.f;
        #pragma unroll
        for (int cc = 0; cc < 8; cc++) O[r][cc] = 0.f;
    }

    for (int j0 = 0; j0 < N_; j0 += 64) {
        __syncthreads();
        for (int t = tid; t < 128*64; t += 256) {
            int c = t >> 6, jj = t & 63;
            size_t src = ((size_t)b * C_ + c) * N_ + j0 + jj;
            Ks[jj*129 + c] = g_k[src];
            Vs[jj*129 + c] = g_v[src];
        }
        __syncthreads();

        // S = Q K^T (64x64), frag 4x4 per thread
        float s[4][4] = {};
        #pragma unroll 4
        for (int c = 0; c < 128; c++) {
            float qr[4], kc[4];
            #pragma unroll
            for (int r = 0; r < 4; r++) qr[r] = Qs[(ty*4 + r)*129 + c];
            #pragma unroll
            for (int j = 0; j < 4; j++) kc[j] = Ks[(tx*4 + j)*129 + c];
            #pragma unroll
            for (int r = 0; r < 4; r++)
                #pragma unroll
                for (int j = 0; j < 4; j++)
                    s[r][j] += qr[r] * kc[j];
        }

        // online softmax per row; reduce across the 16 tx threads (half-warp)
        #pragma unroll
        for (int r = 0; r < 4; r++) {
            float mt = fmaxf(fmaxf(s[r][0], s[r][1]), fmaxf(s[r][2], s[r][3]));
            #pragma unroll
            for (int off = 1; off < 16; off <<= 1)
                mt = fmaxf(mt, __shfl_xor_sync(0xffffffffu, mt, off));
            float mn   = fmaxf(m[r], mt);
            float corr = __expf(m[r] - mn);
            float ps = 0.f;
            #pragma unroll
            for (int j = 0; j < 4; j++) {
                float p = __expf(s[r][j] - mn);
                Ps[(ty*4 + r)*65 + tx*4 + j] = p;
                ps += p;
            }
            #pragma unroll
            for (int off = 1; off < 16; off <<= 1)
                ps += __shfl_xor_sync(0xffffffffu, ps, off);
            l[r] = l[r] * corr + ps;
            m[r] = mn;
            #pragma unroll
            for (int cc = 0; cc < 8; cc++) O[r][cc] *= corr;
        }
        __syncthreads();

        // O += P * V  (P: 64x64 in shared, V^T tile: Vs[j][c])
        #pragma unroll 2
        for (int j = 0; j < 64; j++) {
            float pv[4];
            #pragma unroll
            for (int r = 0; r < 4; r++) pv[r] = Ps[(ty*4 + r)*65 + j];
            #pragma unroll
            for (int cc = 0; cc < 8; cc++) {
                float vv = Vs[j*129 + tx*8 + cc];
                #pragma unroll
                for (int r = 0; r < 4; r++) O[r][cc] += pv[r] * vv;
            }
        }
    }

    // epilogue: divide by l, write g_o[b][c][i]
    #pragma unroll
    for (int r = 0; r < 4; r++) {
        float inv = 1.f / l[r];
        int i = i0 + ty*4 + r;
        #pragma unroll
        for (int cc = 0; cc < 8; cc++) {
            int c = tx*8 + cc;
            g_o[((size_t)b * C_ + c) * N_ + i] = O[r][cc] * inv;
        }
    }
}

// ---------------------------------------------------------------------------
// SE branch: y = mean(x, spatial); y1 = relu(y @ w1^T); y2 = sigmoid(y1 @ w2^T)
// grid: (B), block 256 (8 warps; each warp handles channels warp, warp+8, ...)
// ---------------------------------------------------------------------------
__global__ __launch_bounds__(256) void se_kernel(
    const float* __restrict__ x,
    const float* __restrict__ w1,   // (8, 128)
    const float* __restrict__ w2)   // (128, 8)
{
    __shared__ float y[C_];
    __shared__ float y1[C_/16];
    int b = blockIdx.x;
    int tid = threadIdx.x;
    int warp = tid >> 5, lane = tid & 31;

    for (int c = warp; c < C_; c += 8) {
        const float* row = x + ((size_t)b * C_ + c) * N_;
        float s = 0.f;
        for (int n = lane; n < N_; n += 32) s += row[n];
        #pragma unroll
        for (int off = 16; off > 0; off >>= 1)
            s += __shfl_xor_sync(0xffffffffu, s, off);
        if (lane == 0) y[c] = s / (float)N_;
    }
    __syncthreads();
    if (tid < 8) {
        float a = 0.f;
        for (int c = 0; c < C_; c++) a += w1[tid * C_ + c] * y[c];
        y1[tid] = fmaxf(a, 0.f);
    }
    __syncthreads();
    if (tid < C_) {
        float a = 0.f;
        #pragma unroll
        for (int r = 0; r < 8; r++) a += w2[tid * 8 + r] * y1[r];
        g_se[b * C_ + tid] = 1.f / (1.f + __expf(-a));
    }
}

// ---------------------------------------------------------------------------
// Final combine: out = gamma * attn_out + x * se[b][c]
// ---------------------------------------------------------------------------
__global__ __launch_bounds__(256) void final_kernel(
    const float* __restrict__ x,
    const float* __restrict__ gamma,
    float* __restrict__ out)
{
    float g = gamma[0];
    int total = B_ * C_ * N_;
    for (int idx = blockIdx.x * blockDim.x + threadIdx.x; idx < total;
         idx += gridDim.x * blockDim.x) {
        int bc = idx / N_;
        out[idx] = g * g_o[idx] + x[idx] * g_se[bc];
    }
}

// ---------------------------------------------------------------------------
extern "C" void kernel_launch(void* const* d_in, const int* in_sizes, int n_in,
                              void* d_out, int out_size)
{
    const float* x     = (const float*)d_in[0];
    const float* Wq    = (const float*)d_in[1];
    const float* bq    = (const float*)d_in[2];
    const float* Wk    = (const float*)d_in[3];
    const float* bk    = (const float*)d_in[4];
    const float* Wv    = (const float*)d_in[5];
    const float* bv    = (const float*)d_in[6];
    const float* se_w1 = (const float*)d_in[7];
    const float* se_w2 = (const float*)d_in[8];
    const float* gamma = (const float*)d_in[9];
    float* out = (float*)d_out;

    static int smem_set = 0;
    if (!smem_set) {
        cudaFuncSetAttribute(attn_kernel,
                             cudaFuncAttributeMaxDynamicSharedMemorySize,
                             ATTN_SMEM_FLOATS * (int)sizeof(float));
        smem_set = 1;
    }

    qkv_kernel<<<dim3(NTILES, C_/64, 3*B_), 256>>>(x, Wq, bq, Wk, bk, Wv, bv);
    se_kernel<<<B_, 256>>>(x, se_w1, se_w2);
    attn_kernel<<<dim3(NTILES, B_), 256, ATTN_SMEM_FLOATS * sizeof(float)>>>();
    final_kernel<<<2048, 256>>>(x, gamma, out);
}

// round 2
// speedup vs baseline: 3.7362x; 3.7362x over previous
#include <cuda_runtime.h>
#include <math_constants.h>
#include <cstdint>

#define B_ 8
#define C_ 128
#define N_ 2304
#define BM 128
#define BN 64

// smem strides (floats). SK,SQ,SP ≡ 4 (mod 32), SV ≡ 8 (mod 32) -> conflict-free frags
#define SQ 132
#define SK 132
#define SV 136
#define SP 68

#define OFF_Q   0
#define OFF_K   (OFF_Q + BM*SQ)
#define OFF_V   (OFF_K + 2*BN*SK)
#define OFF_P   (OFF_V + BN*SV)
#define SMEM_FLOATS (OFF_P + BM*SP)   // 51200 floats = 200 KiB

__device__ float g_q[B_*C_*N_];
__device__ float g_k[B_*C_*N_];
__device__ float g_v[B_*C_*N_];
__device__ float g_se[B_*C_];

// ---------------------------------------------------------------------------
__device__ __forceinline__ float tf32r(float x){
    uint32_t u;
    asm volatile("cvt.rna.tf32.f32 %0, %1;" : "=r"(u) : "f"(x));
    return __uint_as_float(u);
}
__device__ __forceinline__ void cpa4(uint32_t s, const float* g){
    asm volatile("cp.async.ca.shared.global [%0], [%1], 4;" :: "r"(s), "l"(g));
}
__device__ __forceinline__ void cp_commit(){ asm volatile("cp.async.commit_group;"); }
__device__ __forceinline__ void cp_wait1(){ asm volatile("cp.async.wait_group 1;"); }
__device__ __forceinline__ void cp_wait0(){ asm volatile("cp.async.wait_group 0;"); }

__device__ __forceinline__ uint32_t lds32(uint32_t a){
    uint32_t v; asm volatile("ld.shared.b32 %0, [%1];" : "=r"(v) : "r"(a)); return v;
}
__device__ __forceinline__ void sts64(uint32_t a, float x, float y){
    asm volatile("st.shared.v2.f32 [%0], {%1,%2};" :: "r"(a), "f"(x), "f"(y));
}
__device__ __forceinline__ void mma8(float* d, uint32_t a0,uint32_t a1,uint32_t a2,uint32_t a3,
                                     uint32_t b0,uint32_t b1){
    asm volatile(
      "mma.sync.aligned.m16n8k8.row.col.f32.tf32.tf32.f32 "
      "{%0,%1,%2,%3}, {%4,%5,%6,%7}, {%8,%9}, {%0,%1,%2,%3};"
      : "+f"(d[0]), "+f"(d[1]), "+f"(d[2]), "+f"(d[3])
      : "r"(a0), "r"(a1), "r"(a2), "r"(a3), "r"(b0), "r"(b1));
}

// ---------------------------------------------------------------------------
// QKV projection (fp32 SIMT), outputs rounded to tf32 (RN) for the MMA stage.
// ---------------------------------------------------------------------------
__global__ __launch_bounds__(256) void qkv_kernel(
    const float* __restrict__ x,
    const float* __restrict__ Wq, const float* __restrict__ bq,
    const float* __restrict__ Wk, const float* __restrict__ bk,
    const float* __restrict__ Wv, const float* __restrict__ bv)
{
    int b = blockIdx.z & 7;
    int which = blockIdx.z >> 3;
    const float* Wm   = (which == 0) ? Wq : (which == 1) ? Wk : Wv;
    const float* bias = (which == 0) ? bq : (which == 1) ? bk : bv;
    float* dst        = (which == 0) ? g_q : (which == 1) ? g_k : g_v;

    int o0 = blockIdx.y * 64;
    int n0 = blockIdx.x * 64;

    __shared__ float Ws[64][33];
    __shared__ float Xs[32][64];

    int tid = threadIdx.x;
    int ty = tid >> 4, tx = tid & 15;

    float acc[4][4] = {};
    const float* xb = x + (size_t)b * C_ * N_;

    for (int k0 = 0; k0 < C_; k0 += 32) {
        for (int t = tid; t < 64*32; t += 256) {
            int oo = t >> 5, kk = t & 31;
            Ws[oo][kk] = Wm[(o0 + oo) * C_ + k0 + kk];
        }
        for (int t = tid; t < 32*64; t += 256) {
            int kk = t >> 6, nn = t & 63;
            Xs[kk][nn] = xb[(size_t)(k0 + kk) * N_ + n0 + nn];
        }
        __syncthreads();
        #pragma unroll
        for (int kk = 0; kk < 32; kk++) {
            float a[4], bb[4];
            #pragma unroll
            for (int r = 0; r < 4; r++) a[r] = Ws[ty*4 + r][kk];
            #pragma unroll
            for (int j = 0; j < 4; j++) bb[j] = Xs[kk][tx*4 + j];
            #pragma unroll
            for (int r = 0; r < 4; r++)
                #pragma unroll
                for (int j = 0; j < 4; j++)
                    acc[r][j] += a[r] * bb[j];
        }
        __syncthreads();
    }

    #pragma unroll
    for (int r = 0; r < 4; r++) {
        int o = o0 + ty*4 + r;
        float bv_ = bias[o];
        #pragma unroll
        for (int j = 0; j < 4; j++) {
            dst[((size_t)b * C_ + o) * N_ + n0 + tx*4 + j] = tf32r(acc[r][j] + bv_);
        }
    }
}

// ---------------------------------------------------------------------------
// SE branch
// ---------------------------------------------------------------------------
__global__ __launch_bounds__(256) void se_kernel(
    const float* __restrict__ x,
    const float* __restrict__ w1,
    const float* __restrict__ w2)
{
    __shared__ float y[C_];
    __shared__ float y1[C_/16];
    int b = blockIdx.x;
    int tid = threadIdx.x;
    int warp = tid >> 5, lane = tid & 31;

    for (int c = warp; c < C_; c += 8) {
        const float* row = x + ((size_t)b * C_ + c) * N_;
        float s = 0.f;
        for (int n = lane; n < N_; n += 32) s += row[n];
        #pragma unroll
        for (int off = 16; off > 0; off >>= 1)
            s += __shfl_xor_sync(0xffffffffu, s, off);
        if (lane == 0) y[c] = s / (float)N_;
    }
    __syncthreads();
    if (tid < 8) {
        float a = 0.f;
        for (int c = 0; c < C_; c++) a += w1[tid * C_ + c] * y[c];
        y1[tid] = fmaxf(a, 0.f);
    }
    __syncthreads();
    if (tid < C_) {
        float a = 0.f;
        #pragma unroll
        for (int r = 0; r < 8; r++) a += w2[tid * 8 + r] * y1[r];
        g_se[b * C_ + tid] = 1.f / (1.f + __expf(-a));
    }
}

// ---------------------------------------------------------------------------
// Flash attention, tf32 warp-MMA, fused final combine.
// grid (N/128, B), block 256 (8 warps x 16 rows).
// ---------------------------------------------------------------------------
__global__ void __launch_bounds__(256, 1) attn_kernel(
    const float* __restrict__ x,
    const float* __restrict__ gamma,
    float* __restrict__ out)
{
    extern __shared__ float sm[];
    uint32_t sb = (uint32_t)__cvta_generic_to_shared(sm);

    const int tid  = threadIdx.x;
    const int b    = blockIdx.y;
    const int i0   = blockIdx.x * BM;
    const int warp = tid >> 5, lane = tid & 31;
    const int quad = lane >> 2, qt = lane & 3;

    // ---- staging lane decompositions ----
    const int w8 = tid >> 5;
    // K: c = (tid>>3 & 3) + 4*w + 32*cc ; j = (tid&7) + 8*jj
    const int k_cl = (tid >> 3) & 3, k_jl = tid & 7;
    // V: c = (tid>>2 & 7) + 8*w + 64*cc ; j = (tid&3) + 4*jj
    const int v_cl = (tid >> 2) & 7, v_jl = tid & 3;

    const size_t bcn = (size_t)b * C_ * N_;

    // ---- prologue: stage Q (128x128) and K tile 0 ----
    {
        // Q: k = (tid>>3 & 3) + 4*w + 32*kk ; i = (tid&7) + 8*ii
        #pragma unroll
        for (int kk = 0; kk < 4; kk++) {
            int k = k_cl + 4*w8 + 32*kk;
            const float* gp = g_q + bcn + (size_t)k * N_ + i0;
            #pragma unroll
            for (int ii = 0; ii < 16; ii++) {
                int i = k_jl + 8*ii;
                cpa4(sb + 4u*(OFF_Q + i*SQ + k), gp + i);
            }
        }
        #pragma unroll
        for (int cc = 0; cc < 4; cc++) {
            int c = k_cl + 4*w8 + 32*cc;
            const float* gp = g_k + bcn + (size_t)c * N_;
            #pragma unroll
            for (int jj = 0; jj < 8; jj++) {
                int j = k_jl + 8*jj;
                cpa4(sb + 4u*(OFF_K + j*SK + c), gp + j);
            }
        }
        cp_commit();
    }

    float o[16][4];
    #pragma unroll
    for (int ct = 0; ct < 16; ct++)
        #pragma unroll
        for (int r = 0; r < 4; r++) o[ct][r] = 0.f;
    float m0 = -CUDART_INF_F, m1 = -CUDART_INF_F, l0 = 0.f, l1 = 0.f;

    const uint32_t qrow  = sb + 4u*(OFF_Q + (warp*16 + quad)*SQ + qt);
    const uint32_t prow  = sb + 4u*(OFF_P + (warp*16 + quad)*SP + qt);
    const uint32_t pst0  = sb + 4u*(OFF_P + (warp*16 + quad)*SP + 2*qt);
    const uint32_t pst1  = pst0 + 4u*8*SP;
    const uint32_t vbase = sb + 4u*OFF_V;

    for (int t = 0; t < 36; t++) {
        const int j0 = t * BN;
        // stage V tile t
        #pragma unroll
        for (int cc = 0; cc < 2; cc++) {
            int c = v_cl + 8*w8 + 64*cc;
            const float* gp = g_v + bcn + (size_t)c * N_ + j0;
            #pragma unroll
            for (int jj = 0; jj < 16; jj++) {
                int j = v_jl + 4*jj;
                cpa4(sb + 4u*(OFF_V + j*SV + c), gp + j);
            }
        }
        cp_commit();

        cp_wait1();            // K_t (and Q) resident
        __syncthreads();

        // ---- S = Q K^T (128x64 per CTA; 16x64 per warp) ----
        float s[8][4];
        #pragma unroll
        for (int nt = 0; nt < 8; nt++)
            #pragma unroll
            for (int r = 0; r < 4; r++) s[nt][r] = 0.f;

        const uint32_t kbuf = sb + 4u*(OFF_K + (t & 1)*BN*SK);
        #pragma unroll
        for (int ks = 0; ks < 16; ks++) {
            uint32_t a0 = lds32(qrow + 4u*(ks*8));
            uint32_t a2 = lds32(qrow + 4u*(ks*8 + 4));
            uint32_t a1 = lds32(qrow + 4u*(8*SQ + ks*8));
            uint32_t a3 = lds32(qrow + 4u*(8*SQ + ks*8 + 4));
            #pragma unroll
            for (int nt = 0; nt < 8; nt++) {
                uint32_t bb0 = lds32(kbuf + 4u*((nt*8 + quad)*SK + ks*8 + qt));
                uint32_t bb1 = lds32(kbuf + 4u*((nt*8 + quad)*SK + ks*8 + qt + 4));
                mma8(s[nt], a0, a1, a2, a3, bb0, bb1);
            }
        }

        // prefetch K tile t+1 into other buffer, then ensure V_t resident
        if (t < 35) {
            #pragma unroll
            for (int cc = 0; cc < 4; cc++) {
                int c = k_cl + 4*w8 + 32*cc;
                const float* gp = g_k + bcn + (size_t)c * N_ + j0 + BN;
                #pragma unroll
                for (int jj = 0; jj < 8; jj++) {
                    int j = k_jl + 8*jj;
                    cpa4(sb + 4u*(OFF_K + ((t+1)&1)*BN*SK + j*SK + c), gp + j);
                }
            }
            cp_commit();
            cp_wait1();
        } else {
            cp_wait0();
        }
        __syncthreads();       // V_t visible to all warps

        // ---- online softmax (rows r0 = warp*16+quad, r1 = r0+8) ----
        float mt0 = -CUDART_INF_F, mt1 = -CUDART_INF_F;
        #pragma unroll
        for (int nt = 0; nt < 8; nt++) {
            mt0 = fmaxf(mt0, fmaxf(s[nt][0], s[nt][1]));
            mt1 = fmaxf(mt1, fmaxf(s[nt][2], s[nt][3]));
        }
        #pragma unroll
        for (int off = 1; off < 4; off <<= 1) {
            mt0 = fmaxf(mt0, __shfl_xor_sync(0xffffffffu, mt0, off));
            mt1 = fmaxf(mt1, __shfl_xor_sync(0xffffffffu, mt1, off));
        }
        float mn0 = fmaxf(m0, mt0), mn1 = fmaxf(m1, mt1);
        float cor0 = __expf(m0 - mn0), cor1 = __expf(m1 - mn1);
        float rs0 = 0.f, rs1 = 0.f;
        #pragma unroll
        for (int nt = 0; nt < 8; nt++) {
            float p00 = tf32r(__expf(s[nt][0] - mn0));
            float p01 = tf32r(__expf(s[nt][1] - mn0));
            float p10 = tf32r(__expf(s[nt][2] - mn1));
            float p11 = tf32r(__expf(s[nt][3] - mn1));
            rs0 += p00 + p01; rs1 += p10 + p11;
            sts64(pst0 + 4u*(nt*8), p00, p01);
            sts64(pst1 + 4u*(nt*8), p10, p11);
        }
        #pragma unroll
        for (int off = 1; off < 4; off <<= 1) {
            rs0 += __shfl_xor_sync(0xffffffffu, rs0, off);
            rs1 += __shfl_xor_sync(0xffffffffu, rs1, off);
        }
        l0 = l0 * cor0 + rs0; m0 = mn0;
        l1 = l1 * cor1 + rs1; m1 = mn1;
        #pragma unroll
        for (int ct = 0; ct < 16; ct++) {
            o[ct][0] *= cor0; o[ct][1] *= cor0;
            o[ct][2] *= cor1; o[ct][3] *= cor1;
        }
        __syncwarp();          // P rows are warp-private; order st->ld

        // ---- O += P V  (16x128 per warp) ----
        #pragma unroll
        for (int kb = 0; kb < 8; kb++) {
            uint32_t a0 = lds32(prow + 4u*(kb*8));
            uint32_t a2 = lds32(prow + 4u*(kb*8 + 4));
            uint32_t a1 = lds32(prow + 4u*(8*SP + kb*8));
            uint32_t a3 = lds32(prow + 4u*(8*SP + kb*8 + 4));
            #pragma unroll
            for (int ct = 0; ct < 16; ct++) {
                uint32_t bb0 = lds32(vbase + 4u*((kb*8 + qt)*SV + ct*8 + quad));
                uint32_t bb1 = lds32(vbase + 4u*((kb*8 + qt + 4)*SV + ct*8 + quad));
                mma8(o[ct], a0, a1, a2, a3, bb0, bb1);
            }
        }
        __syncthreads();       // protect Vs before next iter's staging
    }

    // ---- epilogue: out = gamma * O/l + x * se ----
    const float gam = gamma[0];
    const float inv0 = 1.f / l0, inv1 = 1.f / l1;
    const int ir0 = i0 + warp*16 + quad, ir1 = ir0 + 8;
    #pragma unroll
    for (int ct = 0; ct < 16; ct++) {
        int c0 = ct*8 + qt*2;
        float se0 = g_se[b*C_ + c0], se1 = g_se[b*C_ + c0 + 1];
        size_t base0 = bcn + (size_t)c0 * N_;
        size_t base1 = base0 + N_;
        out[base0 + ir0] = gam * o[ct][0] * inv0 + x[base0 + ir0] * se0;
        out[base1 + ir0] = gam * o[ct][1] * inv0 + x[base1 + ir0] * se1;
        out[base0 + ir1] = gam * o[ct][2] * inv1 + x[base0 + ir1] * se0;
        out[base1 + ir1] = gam * o[ct][3] * inv1 + x[base1 + ir1] * se1;
    }
}

// ---------------------------------------------------------------------------
extern "C" void kernel_launch(void* const* d_in, const int* in_sizes, int n_in,
                              void* d_out, int out_size)
{
    const float* x     = (const float*)d_in[0];
    const float* Wq    = (const float*)d_in[1];
    const float* bq    = (const float*)d_in[2];
    const float* Wk    = (const float*)d_in[3];
    const float* bk    = (const float*)d_in[4];
    const float* Wv    = (const float*)d_in[5];
    const float* bv    = (const float*)d_in[6];
    const float* se_w1 = (const float*)d_in[7];
    const float* se_w2 = (const float*)d_in[8];
    const float* gamma = (const float*)d_in[9];
    float* out = (float*)d_out;

    static int smem_set = 0;
    if (!smem_set) {
        cudaFuncSetAttribute(attn_kernel,
                             cudaFuncAttributeMaxDynamicSharedMemorySize,
                             SMEM_FLOATS * (int)sizeof(float));
        smem_set = 1;
    }

    qkv_kernel<<<dim3(N_/64, C_/64, 3*B_), 256>>>(x, Wq, bq, Wk, bk, Wv, bv);
    se_kernel<<<B_, 256>>>(x, se_w1, se_w2);
    attn_kernel<<<dim3(N_/BM, B_), 256, SMEM_FLOATS * sizeof(float)>>>(x, gamma, out);
}

// round 3
// speedup vs baseline: 6.8386x; 1.8304x over previous
#include <cuda_runtime.h>
#include <cuda_fp16.h>
#include <math_constants.h>
#include <cstdint>

#define B_ 8
#define C_ 128
#define N_ 2304
#define BM 128
#define BN 64

// smem strides in HALFS; all ≡ 4 banks (mod 32) -> conflict-free ldmatrix rows
#define SQh 136
#define SKh 136
#define SVh 72
#define SPh 72

#define OFF_Q 0
#define OFF_K (BM*SQh)                 // 17408
#define OFF_V (OFF_K + 2*BN*SKh)       // 34816
#define OFF_P (OFF_V + C_*SVh)         // 44032
#define SMEM_HALFS (OFF_P + BM*SPh)    // 53248 halfs = 106496 B

__device__ __half g_qh[B_*N_*C_];   // [b][n][c]
__device__ __half g_kh[B_*N_*C_];   // [b][n][c]
__device__ __half g_vh[B_*C_*N_];   // [b][c][n]
__device__ float  g_se[B_*C_];

// ---------------------------------------------------------------------------
__device__ __forceinline__ void cpa16(uint32_t s, const void* g){
    asm volatile("cp.async.cg.shared.global [%0], [%1], 16;" :: "r"(s), "l"(g));
}
__device__ __forceinline__ void cp_commit(){ asm volatile("cp.async.commit_group;"); }
__device__ __forceinline__ void cp_wait1(){ asm volatile("cp.async.wait_group 1;"); }
__device__ __forceinline__ void cp_wait0(){ asm volatile("cp.async.wait_group 0;"); }

__device__ __forceinline__ void ldsm4(uint32_t& r0,uint32_t& r1,uint32_t& r2,uint32_t& r3,
                                      uint32_t a){
    asm volatile("ldmatrix.sync.aligned.m8n8.x4.shared.b16 {%0,%1,%2,%3}, [%4];"
        : "=r"(r0),"=r"(r1),"=r"(r2),"=r"(r3) : "r"(a));
}
__device__ __forceinline__ void sts32(uint32_t a, uint32_t v){
    asm volatile("st.shared.b32 [%0], %1;" :: "r"(a), "r"(v));
}
__device__ __forceinline__ void mma16(float* d, uint32_t a0,uint32_t a1,uint32_t a2,uint32_t a3,
                                      uint32_t b0,uint32_t b1){
    asm volatile(
      "mma.sync.aligned.m16n8k16.row.col.f32.f16.f16.f32 "
      "{%0,%1,%2,%3}, {%4,%5,%6,%7}, {%8,%9}, {%0,%1,%2,%3};"
      : "+f"(d[0]), "+f"(d[1]), "+f"(d[2]), "+f"(d[3])
      : "r"(a0), "r"(a1), "r"(a2), "r"(a3), "r"(b0), "r"(b1));
}
__device__ __forceinline__ uint32_t h2u(__half2 h){ return *reinterpret_cast<uint32_t*>(&h); }

// ---------------------------------------------------------------------------
// QKV projection (fp32 SIMT). q,k written transposed [n][c] fp16 via smem tile;
// v written [c][n] fp16 directly.
// ---------------------------------------------------------------------------
__global__ __launch_bounds__(256) void qkv_kernel(
    const float* __restrict__ x,
    const float* __restrict__ Wq, const float* __restrict__ bq,
    const float* __restrict__ Wk, const float* __restrict__ bk,
    const float* __restrict__ Wv, const float* __restrict__ bv)
{
    int b = blockIdx.z & 7;
    int which = blockIdx.z >> 3;
    const float* Wm   = (which == 0) ? Wq : (which == 1) ? Wk : Wv;
    const float* bias = (which == 0) ? bq : (which == 1) ? bk : bv;

    int o0 = blockIdx.y * 64;
    int n0 = blockIdx.x * 64;

    __shared__ float Ws[64][33];
    __shared__ float Xs[32][64];
    __shared__ __half Ts[64*68];

    int tid = threadIdx.x;
    int ty = tid >> 4, tx = tid & 15;

    float acc[4][4] = {};
    const float* xb = x + (size_t)b * C_ * N_;

    for (int k0 = 0; k0 < C_; k0 += 32) {
        for (int t = tid; t < 64*32; t += 256) {
            int oo = t >> 5, kk = t & 31;
            Ws[oo][kk] = Wm[(o0 + oo) * C_ + k0 + kk];
        }
        for (int t = tid; t < 32*64; t += 256) {
            int kk = t >> 6, nn = t & 63;
            Xs[kk][nn] = xb[(size_t)(k0 + kk) * N_ + n0 + nn];
        }
        __syncthreads();
        #pragma unroll
        for (int kk = 0; kk < 32; kk++) {
            float a[4], bb[4];
            #pragma unroll
            for (int r = 0; r < 4; r++) a[r] = Ws[ty*4 + r][kk];
            #pragma unroll
            for (int j = 0; j < 4; j++) bb[j] = Xs[kk][tx*4 + j];
            #pragma unroll
            for (int r = 0; r < 4; r++)
                #pragma unroll
                for (int j = 0; j < 4; j++)
                    acc[r][j] += a[r] * bb[j];
        }
        __syncthreads();
    }

    if (which == 2) {
        // v: [c][n] direct
        #pragma unroll
        for (int r = 0; r < 4; r++) {
            int o = o0 + ty*4 + r;
            float bv_ = bias[o];
            __half2* dst = (__half2*)(g_vh + ((size_t)b*C_ + o)*N_ + n0 + tx*4);
            dst[0] = __floats2half2_rn(acc[r][0] + bv_, acc[r][1] + bv_);
            dst[1] = __floats2half2_rn(acc[r][2] + bv_, acc[r][3] + bv_);
        }
    } else {
        __half* dsth = (which == 0) ? g_qh : g_kh;
        #pragma unroll
        for (int r = 0; r < 4; r++) {
            int oo = ty*4 + r;
            float bv_ = bias[o0 + oo];
            __half2* t2 = (__half2*)&Ts[oo*68 + tx*4];
            t2[0] = __floats2half2_rn(acc[r][0] + bv_, acc[r][1] + bv_);
            t2[1] = __floats2half2_rn(acc[r][2] + bv_, acc[r][3] + bv_);
        }
        __syncthreads();
        // transposed write: 512 chunks of 16B (8 o-values at fixed n)
        #pragma unroll
        for (int w2 = 0; w2 < 2; w2++) {
            int ch = tid + w2*256;
            int n = ch >> 3, ob = ch & 7;
            __half tmp[8];
            #pragma unroll
            for (int u = 0; u < 8; u++) tmp[u] = Ts[(ob*8 + u)*68 + n];
            *(uint4*)(dsth + ((size_t)b*N_ + n0 + n)*C_ + o0 + ob*8) = *(uint4*)tmp;
        }
    }
}

// ---------------------------------------------------------------------------
// SE branch
// ---------------------------------------------------------------------------
__global__ __launch_bounds__(256) void se_kernel(
    const float* __restrict__ x,
    const float* __restrict__ w1,
    const float* __restrict__ w2)
{
    __shared__ float y[C_];
    __shared__ float y1[C_/16];
    int b = blockIdx.x;
    int tid = threadIdx.x;
    int warp = tid >> 5, lane = tid & 31;

    for (int c = warp; c < C_; c += 8) {
        const float* row = x + ((size_t)b * C_ + c) * N_;
        float s = 0.f;
        for (int n = lane; n < N_; n += 32) s += row[n];
        #pragma unroll
        for (int off = 16; off > 0; off >>= 1)
            s += __shfl_xor_sync(0xffffffffu, s, off);
        if (lane == 0) y[c] = s / (float)N_;
    }
    __syncthreads();
    if (tid < 8) {
        float a = 0.f;
        for (int c = 0; c < C_; c++) a += w1[tid * C_ + c] * y[c];
        y1[tid] = fmaxf(a, 0.f);
    }
    __syncthreads();
    if (tid < C_) {
        float a = 0.f;
        #pragma unroll
        for (int r = 0; r < 8; r++) a += w2[tid * 8 + r] * y1[r];
        g_se[b * C_ + tid] = 1.f / (1.f + __expf(-a));
    }
}

// ---------------------------------------------------------------------------
// Flash attention, fp16 m16n8k16 + ldmatrix, fused final combine.
// grid (N/128, B), block 256 (8 warps x 16 rows).
// ---------------------------------------------------------------------------
__global__ void __launch_bounds__(256, 1) attn_kernel(
    const float* __restrict__ x,
    const float* __restrict__ gamma,
    float* __restrict__ out)
{
    extern __shared__ __half smh[];
    uint32_t sb = (uint32_t)__cvta_generic_to_shared(smh);

    const int tid  = threadIdx.x;
    const int b    = blockIdx.y;
    const int i0   = blockIdx.x * BM;
    const int warp = tid >> 5, lane = tid & 31;
    const int quad = lane >> 2, qt = lane & 3;

    const size_t bcn = (size_t)b * C_ * N_;
    const __half* qb = g_qh + (size_t)b * N_ * C_;
    const __half* kb = g_kh + (size_t)b * N_ * C_;
    const __half* vb = g_vh + (size_t)b * C_ * N_;

    // ---- prologue: stage Q [i][c] (128x128) + K tile 0 [j][c] ----
    #pragma unroll
    for (int c2 = 0; c2 < 8; c2++) {
        int ch = tid + c2*256;
        int i = ch >> 4, cb = ch & 15;
        cpa16(sb + 2u*(OFF_Q + i*SQh + cb*8), qb + (size_t)(i0 + i)*C_ + cb*8);
    }
    #pragma unroll
    for (int c2 = 0; c2 < 4; c2++) {
        int ch = tid + c2*256;
        int j = ch >> 4, cb = ch & 15;
        cpa16(sb + 2u*(OFF_K + j*SKh + cb*8), kb + (size_t)j*C_ + cb*8);
    }
    cp_commit();

    float o[16][4];
    #pragma unroll
    for (int ct = 0; ct < 16; ct++)
        #pragma unroll
        for (int r = 0; r < 4; r++) o[ct][r] = 0.f;
    float m0 = -CUDART_INF_F, m1 = -CUDART_INF_F, l0 = 0.f, l1 = 0.f;

    // ldmatrix address lanes
    const int r16  = lane & 15;                          // A rows
    const int ahi  = (lane >> 4) * 8;                    // A col offset (halfs)
    const int brow = (lane & 7) + ((lane >> 4) & 1) * 8; // B rows within 16
    const int bcol = ((lane >> 3) & 1) * 8;              // B col offset

    const uint32_t aQ  = sb + 2u*(OFF_Q + (warp*16 + r16)*SQh + ahi);
    const uint32_t aP  = sb + 2u*(OFF_P + (warp*16 + r16)*SPh + ahi);
    const uint32_t vB  = sb + 2u*(OFF_V + brow*SVh + bcol);
    const uint32_t pst0 = sb + 2u*(OFF_P + (warp*16 + quad)*SPh + qt*2);
    const uint32_t pst1 = pst0 + 2u*8*SPh;

    for (int t = 0; t < 36; t++) {
        const int j0 = t * BN;
        // stage V tile [c][j] (128x64)
        #pragma unroll
        for (int c2 = 0; c2 < 4; c2++) {
            int ch = tid + c2*256;
            int c = ch >> 3, cb = ch & 7;
            cpa16(sb + 2u*(OFF_V + c*SVh + cb*8), vb + (size_t)c*N_ + j0 + cb*8);
        }
        cp_commit();

        cp_wait1();            // K_t (and Q) resident
        __syncthreads();

        // ---- S = Q K^T ----
        float s[8][4];
        #pragma unroll
        for (int nt = 0; nt < 8; nt++)
            #pragma unroll
            for (int r = 0; r < 4; r++) s[nt][r] = 0.f;

        const uint32_t kB = sb + 2u*(OFF_K + (t & 1)*BN*SKh + brow*SKh + bcol);
        #pragma unroll
        for (int kc = 0; kc < 8; kc++) {
            uint32_t a0,a1,a2,a3;
            ldsm4(a0,a1,a2,a3, aQ + 32u*kc);
            #pragma unroll
            for (int np = 0; np < 4; np++) {
                uint32_t b0,b1,b2,b3;
                ldsm4(b0,b1,b2,b3, kB + 2u*(np*16*SKh + kc*16));
                mma16(s[2*np],   a0,a1,a2,a3, b0,b1);
                mma16(s[2*np+1], a0,a1,a2,a3, b2,b3);
            }
        }

        // prefetch K tile t+1
        if (t < 35) {
            #pragma unroll
            for (int c2 = 0; c2 < 4; c2++) {
                int ch = tid + c2*256;
                int j = ch >> 4, cb = ch & 15;
                cpa16(sb + 2u*(OFF_K + ((t+1)&1)*BN*SKh + j*SKh + cb*8),
                      kb + (size_t)(j0 + BN + j)*C_ + cb*8);
            }
            cp_commit();
            cp_wait1();        // V_t resident
        } else {
            cp_wait0();
        }
        __syncthreads();

        // ---- online softmax; rows r0 = warp*16+quad, r1 = r0+8 ----
        float mt0 = -CUDART_INF_F, mt1 = -CUDART_INF_F;
        #pragma unroll
        for (int nt = 0; nt < 8; nt++) {
            mt0 = fmaxf(mt0, fmaxf(s[nt][0], s[nt][1]));
            mt1 = fmaxf(mt1, fmaxf(s[nt][2], s[nt][3]));
        }
        #pragma unroll
        for (int off = 1; off < 4; off <<= 1) {
            mt0 = fmaxf(mt0, __shfl_xor_sync(0xffffffffu, mt0, off));
            mt1 = fmaxf(mt1, __shfl_xor_sync(0xffffffffu, mt1, off));
        }
        float mn0 = fmaxf(m0, mt0), mn1 = fmaxf(m1, mt1);
        float cor0 = __expf(m0 - mn0), cor1 = __expf(m1 - mn1);
        float rs0 = 0.f, rs1 = 0.f;
        #pragma unroll
        for (int nt = 0; nt < 8; nt++) {
            float p00 = __expf(s[nt][0] - mn0);
            float p01 = __expf(s[nt][1] - mn0);
            float p10 = __expf(s[nt][2] - mn1);
            float p11 = __expf(s[nt][3] - mn1);
            rs0 += p00 + p01; rs1 += p10 + p11;
            sts32(pst0 + 16u*nt, h2u(__floats2half2_rn(p00, p01)));
            sts32(pst1 + 16u*nt, h2u(__floats2half2_rn(p10, p11)));
        }
        #pragma unroll
        for (int off = 1; off < 4; off <<= 1) {
            rs0 += __shfl_xor_sync(0xffffffffu, rs0, off);
            rs1 += __shfl_xor_sync(0xffffffffu, rs1, off);
        }
        l0 = l0 * cor0 + rs0; m0 = mn0;
        l1 = l1 * cor1 + rs1; m1 = mn1;
        #pragma unroll
        for (int ct = 0; ct < 16; ct++) {
            o[ct][0] *= cor0; o[ct][1] *= cor0;
            o[ct][2] *= cor1; o[ct][3] *= cor1;
        }
        __syncwarp();          // P rows warp-private: order st -> ldmatrix

        // ---- O += P V ----
        #pragma unroll
        for (int kc = 0; kc < 4; kc++) {
            uint32_t a0,a1,a2,a3;
            ldsm4(a0,a1,a2,a3, aP + 32u*kc);
            #pragma unroll
            for (int np = 0; np < 8; np++) {
                uint32_t b0,b1,b2,b3;
                ldsm4(b0,b1,b2,b3, vB + 2u*(np*16*SVh + kc*16));
                mma16(o[2*np],   a0,a1,a2,a3, b0,b1);
                mma16(o[2*np+1], a0,a1,a2,a3, b2,b3);
            }
        }
        __syncthreads();       // protect V/P before next iter staging
    }

    // ---- epilogue: out = gamma * O/l + x * se ----
    const float gam = gamma[0];
    const float inv0 = 1.f / l0, inv1 = 1.f / l1;
    const int ir0 = i0 + warp*16 + quad, ir1 = ir0 + 8;
    #pragma unroll
    for (int ct = 0; ct < 16; ct++) {
        int c0 = ct*8 + qt*2;
        float se0 = g_se[b*C_ + c0], se1 = g_se[b*C_ + c0 + 1];
        size_t base0 = bcn + (size_t)c0 * N_;
        size_t base1 = base0 + N_;
        out[base0 + ir0] = gam * o[ct][0] * inv0 + x[base0 + ir0] * se0;
        out[base1 + ir0] = gam * o[ct][1] * inv0 + x[base1 + ir0] * se1;
        out[base0 + ir1] = gam * o[ct][2] * inv1 + x[base0 + ir1] * se0;
        out[base1 + ir1] = gam * o[ct][3] * inv1 + x[base1 + ir1] * se1;
    }
}

// ---------------------------------------------------------------------------
extern "C" void kernel_launch(void* const* d_in, const int* in_sizes, int n_in,
                              void* d_out, int out_size)
{
    const float* x     = (const float*)d_in[0];
    const float* Wq    = (const float*)d_in[1];
    const float* bq    = (const float*)d_in[2];
    const float* Wk    = (const float*)d_in[3];
    const float* bk    = (const float*)d_in[4];
    const float* Wv    = (const float*)d_in[5];
    const float* bv    = (const float*)d_in[6];
    const float* se_w1 = (const float*)d_in[7];
    const float* se_w2 = (const float*)d_in[8];
    const float* gamma = (const float*)d_in[9];
    float* out = (float*)d_out;

    static int smem_set = 0;
    if (!smem_set) {
        cudaFuncSetAttribute(attn_kernel,
                             cudaFuncAttributeMaxDynamicSharedMemorySize,
                             SMEM_HALFS * (int)sizeof(__half));
        smem_set = 1;
    }

    qkv_kernel<<<dim3(N_/64, C_/64, 3*B_), 256>>>(x, Wq, bq, Wk, bk, Wv, bv);
    se_kernel<<<B_, 256>>>(x, se_w1, se_w2);
    attn_kernel<<<dim3(N_/BM, B_), 256, SMEM_HALFS * sizeof(__half)>>>(x, gamma, out);
}

// round 4
// speedup vs baseline: 8.6801x; 1.2693x over previous
#include <cuda_runtime.h>
#include <cuda_fp16.h>
#include <math_constants.h>
#include <cstdint>

#define B_ 8
#define C_ 128
#define N_ 2304
#define BM 128
#define BN 64

// ---------------- attention smem strides (halfs) ----------------
#define SQh 136
#define SKh 136
#define SVh 72
#define SPh 72
#define OFF_Q 0
#define OFF_K (BM*SQh)
#define OFF_V (OFF_K + 2*BN*SKh)
#define OFF_P (OFF_V + C_*SVh)
#define SMEM_HALFS (OFF_P + BM*SPh)

// ---------------- qkv smem strides (halfs) ----------------
#define SX 136
#define SW 136
#define ST 136
#define QOFF_X  0
#define QOFF_W0 (C_*SX)
#define QOFF_W1 (QOFF_W0 + C_*SW)
#define QOFF_T  (QOFF_W1 + C_*SW)
#define QKV_SMEM_HALFS (QOFF_T + C_*ST)   // 69632 halfs = 139264 B

__device__ __half g_qh[B_*N_*C_];   // [b][n][c]
__device__ __half g_kh[B_*N_*C_];   // [b][n][c]
__device__ __half g_vh[B_*C_*N_];   // [b][c][n]
__device__ __half g_xh[B_*C_*N_];   // [b][c][n]
__device__ __half g_wh[3*C_*C_];    // [which][o][c]
__device__ float  g_se[B_*C_];

// ---------------------------------------------------------------------------
__device__ __forceinline__ void cpa16(uint32_t s, const void* g){
    asm volatile("cp.async.cg.shared.global [%0], [%1], 16;" :: "r"(s), "l"(g));
}
__device__ __forceinline__ void cp_commit(){ asm volatile("cp.async.commit_group;"); }
__device__ __forceinline__ void cp_wait1(){ asm volatile("cp.async.wait_group 1;"); }
__device__ __forceinline__ void cp_wait0(){ asm volatile("cp.async.wait_group 0;"); }

__device__ __forceinline__ void ldsm4(uint32_t& r0,uint32_t& r1,uint32_t& r2,uint32_t& r3,
                                      uint32_t a){
    asm volatile("ldmatrix.sync.aligned.m8n8.x4.shared.b16 {%0,%1,%2,%3}, [%4];"
        : "=r"(r0),"=r"(r1),"=r"(r2),"=r"(r3) : "r"(a));
}
__device__ __forceinline__ void ldsm4t(uint32_t& r0,uint32_t& r1,uint32_t& r2,uint32_t& r3,
                                       uint32_t a){
    asm volatile("ldmatrix.sync.aligned.m8n8.x4.trans.shared.b16 {%0,%1,%2,%3}, [%4];"
        : "=r"(r0),"=r"(r1),"=r"(r2),"=r"(r3) : "r"(a));
}
__device__ __forceinline__ void sts32(uint32_t a, uint32_t v){
    asm volatile("st.shared.b32 [%0], %1;" :: "r"(a), "r"(v));
}
__device__ __forceinline__ void mma16(float* d, uint32_t a0,uint32_t a1,uint32_t a2,uint32_t a3,
                                      uint32_t b0,uint32_t b1){
    asm volatile(
      "mma.sync.aligned.m16n8k16.row.col.f32.f16.f16.f32 "
      "{%0,%1,%2,%3}, {%4,%5,%6,%7}, {%8,%9}, {%0,%1,%2,%3};"
      : "+f"(d[0]), "+f"(d[1]), "+f"(d[2]), "+f"(d[3])
      : "r"(a0), "r"(a1), "r"(a2), "r"(a3), "r"(b0), "r"(b1));
}
__device__ __forceinline__ uint32_t h2u(__half2 h){ return *reinterpret_cast<uint32_t*>(&h); }

// ---------------------------------------------------------------------------
// prep: fp32 -> fp16 for x and the 3 weight matrices
// ---------------------------------------------------------------------------
#define X2_TOTAL (B_*C_*N_/2)    // 1179648 half2 chunks
#define W2_TOTAL (3*C_*C_/2)     // 24576
__global__ __launch_bounds__(256) void prep_kernel(
    const float* __restrict__ x,
    const float* __restrict__ Wq,
    const float* __restrict__ Wk,
    const float* __restrict__ Wv)
{
    int idx = blockIdx.x * 256 + threadIdx.x;
    if (idx < X2_TOTAL) {
        float2 v = ((const float2*)x)[idx];
        ((__half2*)g_xh)[idx] = __floats2half2_rn(v.x, v.y);
    } else if (idx < X2_TOTAL + W2_TOTAL) {
        int wi = idx - X2_TOTAL;
        int which = wi / (C_*C_/2);
        int r = wi - which * (C_*C_/2);
        const float* Wm = (which == 0) ? Wq : (which == 1) ? Wk : Wv;
        float2 v = ((const float2*)Wm)[r];
        ((__half2*)g_wh)[wi] = __floats2half2_rn(v.x, v.y);
    }
}

// ---------------------------------------------------------------------------
// QKV via fp16 tensor cores. grid (N/128, B), block 256 (8 warps).
// Per CTA: x tile [c=128][n=128], 3 GEMMs out = W * xtile (+bias).
// ---------------------------------------------------------------------------
__global__ void __launch_bounds__(256, 1) qkv_mma_kernel(
    const float* __restrict__ bq,
    const float* __restrict__ bk,
    const float* __restrict__ bv)
{
    extern __shared__ __half smh[];
    uint32_t sb = (uint32_t)__cvta_generic_to_shared(smh);

    const int tid  = threadIdx.x;
    const int b    = blockIdx.y;
    const int n0   = blockIdx.x * 128;
    const int warp = tid >> 5, lane = tid & 31;
    const int quad = lane >> 2, qt = lane & 3;

    const __half* xb = g_xh + (size_t)b * C_ * N_;

    // stage x tile [c][n] and W0
    #pragma unroll
    for (int c2 = 0; c2 < 8; c2++) {
        int ch = tid + c2*256;
        int c = ch >> 4, nb = ch & 15;
        cpa16(sb + 2u*(QOFF_X + c*SX + nb*8), xb + (size_t)c*N_ + n0 + nb*8);
    }
    #pragma unroll
    for (int c2 = 0; c2 < 8; c2++) {
        int ch = tid + c2*256;
        int o = ch >> 4, cb = ch & 15;
        cpa16(sb + 2u*(QOFF_W0 + o*SW + cb*8), g_wh + o*C_ + cb*8);
    }
    cp_commit();
    cp_wait0();
    __syncthreads();

    // prefetch W1
    #pragma unroll
    for (int c2 = 0; c2 < 8; c2++) {
        int ch = tid + c2*256;
        int o = ch >> 4, cb = ch & 15;
        cpa16(sb + 2u*(QOFF_W1 + o*SW + cb*8), g_wh + C_*C_ + o*C_ + cb*8);
    }
    cp_commit();

    const int r16 = lane & 15;
    const int hi8 = (lane >> 4) * 8;
    const uint32_t bX = sb + 2u*(QOFF_X + r16*SX + hi8);
    const uint32_t tst0 = sb + 2u*(QOFF_T + (warp*16 + quad)*ST + qt*2);
    const uint32_t tst1 = tst0 + 2u*8*ST;

    const int o_r0 = warp*16 + quad, o_r1 = o_r0 + 8;

    #pragma unroll
    for (int which = 0; which < 3; which++) {
        const uint32_t wbuf = sb + 2u*((which & 1) ? QOFF_W1 : QOFF_W0) ;
        const uint32_t aW = wbuf + 2u*((warp*16 + r16)*SW + hi8);

        float acc[16][4];
        #pragma unroll
        for (int nt = 0; nt < 16; nt++)
            #pragma unroll
            for (int r = 0; r < 4; r++) acc[nt][r] = 0.f;

        #pragma unroll
        for (int kc = 0; kc < 8; kc++) {
            uint32_t a0,a1,a2,a3;
            ldsm4(a0,a1,a2,a3, aW + 32u*kc);
            #pragma unroll
            for (int nt16 = 0; nt16 < 8; nt16++) {
                uint32_t b0,b1,b2,b3;
                ldsm4t(b0,b1,b2,b3, bX + 2u*(kc*16*SX + nt16*16));
                mma16(acc[2*nt16],   a0,a1,a2,a3, b0,b1);
                mma16(acc[2*nt16+1], a0,a1,a2,a3, b2,b3);
            }
        }

        // prefetch next W into the buffer not in use (which+2 -> buf (which&1)^... )
        if (which == 0) {
            // W2 -> buf0 (buf0 free after GEMM0 done)
            // must not overwrite while other warps still read: sync first
        }

        // stage to Ts[o][n] with bias
        const float* bias = (which == 0) ? bq : (which == 1) ? bk : bv;
        float b0f = bias[o_r0], b1f = bias[o_r1];
        #pragma unroll
        for (int nt = 0; nt < 16; nt++) {
            sts32(tst0 + 16u*nt, h2u(__floats2half2_rn(acc[nt][0] + b0f, acc[nt][1] + b0f)));
            sts32(tst1 + 16u*nt, h2u(__floats2half2_rn(acc[nt][2] + b1f, acc[nt][3] + b1f)));
        }
        __syncthreads();

        // issue next-next W load now that GEMM(which) is done reading its buffer
        if (which < 2) {
            if (which == 0) {
                #pragma unroll
                for (int c2 = 0; c2 < 8; c2++) {
                    int ch = tid + c2*256;
                    int o = ch >> 4, cb = ch & 15;
                    cpa16(sb + 2u*(QOFF_W0 + o*SW + cb*8), g_wh + 2*C_*C_ + o*C_ + cb*8);
                }
                cp_commit();
            }
        }

        // gmem writes from Ts
        if (which < 2) {
            __half* dsth = (which == 0) ? g_qh : g_kh;
            #pragma unroll
            for (int c2 = 0; c2 < 8; c2++) {
                int ch = tid + c2*256;
                int n = ch >> 4, ob = ch & 15;
                __half tmp[8];
                #pragma unroll
                for (int u = 0; u < 8; u++) tmp[u] = smh[QOFF_T + (ob*8 + u)*ST + n];
                *(uint4*)(dsth + ((size_t)b*N_ + n0 + n)*C_ + ob*8) = *(uint4*)tmp;
            }
        } else {
            #pragma unroll
            for (int c2 = 0; c2 < 8; c2++) {
                int ch = tid + c2*256;
                int o = ch >> 4, nb = ch & 15;
                uint4 v = *(uint4*)&smh[QOFF_T + o*ST + nb*8];
                *(uint4*)(g_vh + ((size_t)b*C_ + o)*N_ + n0 + nb*8) = v;
            }
        }

        if (which < 2) { cp_wait0(); }
        __syncthreads();   // Ts consumed; next W resident
    }
}

// ---------------------------------------------------------------------------
// SE branch
// ---------------------------------------------------------------------------
__global__ __launch_bounds__(256) void se_kernel(
    const float* __restrict__ x,
    const float* __restrict__ w1,
    const float* __restrict__ w2)
{
    __shared__ float y[C_];
    __shared__ float y1[C_/16];
    int b = blockIdx.x;
    int tid = threadIdx.x;
    int warp = tid >> 5, lane = tid & 31;

    for (int c = warp; c < C_; c += 8) {
        const float* row = x + ((size_t)b * C_ + c) * N_;
        float s = 0.f;
        for (int n = lane; n < N_; n += 32) s += row[n];
        #pragma unroll
        for (int off = 16; off > 0; off >>= 1)
            s += __shfl_xor_sync(0xffffffffu, s, off);
        if (lane == 0) y[c] = s / (float)N_;
    }
    __syncthreads();
    if (tid < 8) {
        float a = 0.f;
        for (int c = 0; c < C_; c++) a += w1[tid * C_ + c] * y[c];
        y1[tid] = fmaxf(a, 0.f);
    }
    __syncthreads();
    if (tid < C_) {
        float a = 0.f;
        #pragma unroll
        for (int r = 0; r < 8; r++) a += w2[tid * 8 + r] * y1[r];
        g_se[b * C_ + tid] = 1.f / (1.f + __expf(-a));
    }
}

// ---------------------------------------------------------------------------
// Flash attention, fp16 m16n8k16 + ldmatrix, fused final combine.
// ---------------------------------------------------------------------------
__global__ void __launch_bounds__(256, 1) attn_kernel(
    const float* __restrict__ x,
    const float* __restrict__ gamma,
    float* __restrict__ out)
{
    extern __shared__ __half smh[];
    uint32_t sb = (uint32_t)__cvta_generic_to_shared(smh);

    const int tid  = threadIdx.x;
    const int b    = blockIdx.y;
    const int i0   = blockIdx.x * BM;
    const int warp = tid >> 5, lane = tid & 31;
    const int quad = lane >> 2, qt = lane & 3;

    const size_t bcn = (size_t)b * C_ * N_;
    const __half* qb = g_qh + (size_t)b * N_ * C_;
    const __half* kb = g_kh + (size_t)b * N_ * C_;
    const __half* vb = g_vh + (size_t)b * C_ * N_;

    #pragma unroll
    for (int c2 = 0; c2 < 8; c2++) {
        int ch = tid + c2*256;
        int i = ch >> 4, cb = ch & 15;
        cpa16(sb + 2u*(OFF_Q + i*SQh + cb*8), qb + (size_t)(i0 + i)*C_ + cb*8);
    }
    #pragma unroll
    for (int c2 = 0; c2 < 4; c2++) {
        int ch = tid + c2*256;
        int j = ch >> 4, cb = ch & 15;
        cpa16(sb + 2u*(OFF_K + j*SKh + cb*8), kb + (size_t)j*C_ + cb*8);
    }
    cp_commit();

    float o[16][4];
    #pragma unroll
    for (int ct = 0; ct < 16; ct++)
        #pragma unroll
        for (int r = 0; r < 4; r++) o[ct][r] = 0.f;
    float m0 = -CUDART_INF_F, m1 = -CUDART_INF_F, l0 = 0.f, l1 = 0.f;

    const int r16  = lane & 15;
    const int ahi  = (lane >> 4) * 8;
    const int brow = (lane & 7) + ((lane >> 4) & 1) * 8;
    const int bcol = ((lane >> 3) & 1) * 8;

    const uint32_t aQ  = sb + 2u*(OFF_Q + (warp*16 + r16)*SQh + ahi);
    const uint32_t aP  = sb + 2u*(OFF_P + (warp*16 + r16)*SPh + ahi);
    const uint32_t vB  = sb + 2u*(OFF_V + brow*SVh + bcol);
    const uint32_t pst0 = sb + 2u*(OFF_P + (warp*16 + quad)*SPh + qt*2);
    const uint32_t pst1 = pst0 + 2u*8*SPh;

    for (int t = 0; t < 36; t++) {
        const int j0 = t * BN;
        #pragma unroll
        for (int c2 = 0; c2 < 4; c2++) {
            int ch = tid + c2*256;
            int c = ch >> 3, cb = ch & 7;
            cpa16(sb + 2u*(OFF_V + c*SVh + cb*8), vb + (size_t)c*N_ + j0 + cb*8);
        }
        cp_commit();

        cp_wait1();
        __syncthreads();

        float s[8][4];
        #pragma unroll
        for (int nt = 0; nt < 8; nt++)
            #pragma unroll
            for (int r = 0; r < 4; r++) s[nt][r] = 0.f;

        const uint32_t kB = sb + 2u*(OFF_K + (t & 1)*BN*SKh + brow*SKh + bcol);
        #pragma unroll
        for (int kc = 0; kc < 8; kc++) {
            uint32_t a0,a1,a2,a3;
            ldsm4(a0,a1,a2,a3, aQ + 32u*kc);
            #pragma unroll
            for (int np = 0; np < 4; np++) {
                uint32_t b0,b1,b2,b3;
                ldsm4(b0,b1,b2,b3, kB + 2u*(np*16*SKh + kc*16));
                mma16(s[2*np],   a0,a1,a2,a3, b0,b1);
                mma16(s[2*np+1], a0,a1,a2,a3, b2,b3);
            }
        }

        if (t < 35) {
            #pragma unroll
            for (int c2 = 0; c2 < 4; c2++) {
                int ch = tid + c2*256;
                int j = ch >> 4, cb = ch & 15;
                cpa16(sb + 2u*(OFF_K + ((t+1)&1)*BN*SKh + j*SKh + cb*8),
                      kb + (size_t)(j0 + BN + j)*C_ + cb*8);
            }
            cp_commit();
            cp_wait1();
        } else {
            cp_wait0();
        }
        __syncthreads();

        float mt0 = -CUDART_INF_F, mt1 = -CUDART_INF_F;
        #pragma unroll
        for (int nt = 0; nt < 8; nt++) {
            mt0 = fmaxf(mt0, fmaxf(s[nt][0], s[nt][1]));
            mt1 = fmaxf(mt1, fmaxf(s[nt][2], s[nt][3]));
        }
        #pragma unroll
        for (int off = 1; off < 4; off <<= 1) {
            mt0 = fmaxf(mt0, __shfl_xor_sync(0xffffffffu, mt0, off));
            mt1 = fmaxf(mt1, __shfl_xor_sync(0xffffffffu, mt1, off));
        }
        float mn0 = fmaxf(m0, mt0), mn1 = fmaxf(m1, mt1);
        float cor0 = __expf(m0 - mn0), cor1 = __expf(m1 - mn1);
        float rs0 = 0.f, rs1 = 0.f;
        #pragma unroll
        for (int nt = 0; nt < 8; nt++) {
            float p00 = __expf(s[nt][0] - mn0);
            float p01 = __expf(s[nt][1] - mn0);
            float p10 = __expf(s[nt][2] - mn1);
            float p11 = __expf(s[nt][3] - mn1);
            rs0 += p00 + p01; rs1 += p10 + p11;
            sts32(pst0 + 16u*nt, h2u(__floats2half2_rn(p00, p01)));
            sts32(pst1 + 16u*nt, h2u(__floats2half2_rn(p10, p11)));
        }
        #pragma unroll
        for (int off = 1; off < 4; off <<= 1) {
            rs0 += __shfl_xor_sync(0xffffffffu, rs0, off);
            rs1 += __shfl_xor_sync(0xffffffffu, rs1, off);
        }
        l0 = l0 * cor0 + rs0; m0 = mn0;
        l1 = l1 * cor1 + rs1; m1 = mn1;
        #pragma unroll
        for (int ct = 0; ct < 16; ct++) {
            o[ct][0] *= cor0; o[ct][1] *= cor0;
            o[ct][2] *= cor1; o[ct][3] *= cor1;
        }
        __syncwarp();

        #pragma unroll
        for (int kc = 0; kc < 4; kc++) {
            uint32_t a0,a1,a2,a3;
            ldsm4(a0,a1,a2,a3, aP + 32u*kc);
            #pragma unroll
            for (int np = 0; np < 8; np++) {
                uint32_t b0,b1,b2,b3;
                ldsm4(b0,b1,b2,b3, vB + 2u*(np*16*SVh + kc*16));
                mma16(o[2*np],   a0,a1,a2,a3, b0,b1);
                mma16(o[2*np+1], a0,a1,a2,a3, b2,b3);
            }
        }
        __syncthreads();
    }

    const float gam = gamma[0];
    const float inv0 = 1.f / l0, inv1 = 1.f / l1;
    const int ir0 = i0 + warp*16 + quad, ir1 = ir0 + 8;
    #pragma unroll
    for (int ct = 0; ct < 16; ct++) {
        int c0 = ct*8 + qt*2;
        float se0 = g_se[b*C_ + c0], se1 = g_se[b*C_ + c0 + 1];
        size_t base0 = bcn + (size_t)c0 * N_;
        size_t base1 = base0 + N_;
        out[base0 + ir0] = gam * o[ct][0] * inv0 + x[base0 + ir0] * se0;
        out[base1 + ir0] = gam * o[ct][1] * inv0 + x[base1 + ir0] * se1;
        out[base0 + ir1] = gam * o[ct][2] * inv1 + x[base0 + ir1] * se0;
        out[base1 + ir1] = gam * o[ct][3] * inv1 + x[base1 + ir1] * se1;
    }
}

// ---------------------------------------------------------------------------
extern "C" void kernel_launch(void* const* d_in, const int* in_sizes, int n_in,
                              void* d_out, int out_size)
{
    const float* x     = (const float*)d_in[0];
    const float* Wq    = (const float*)d_in[1];
    const float* bq    = (const float*)d_in[2];
    const float* Wk    = (const float*)d_in[3];
    const float* bk    = (const float*)d_in[4];
    const float* Wv    = (const float*)d_in[5];
    const float* bv    = (const float*)d_in[6];
    const float* se_w1 = (const float*)d_in[7];
    const float* se_w2 = (const float*)d_in[8];
    const float* gamma = (const float*)d_in[9];
    float* out = (float*)d_out;

    static int smem_set = 0;
    if (!smem_set) {
        cudaFuncSetAttribute(attn_kernel,
                             cudaFuncAttributeMaxDynamicSharedMemorySize,
                             SMEM_HALFS * (int)sizeof(__half));
        cudaFuncSetAttribute(qkv_mma_kernel,
                             cudaFuncAttributeMaxDynamicSharedMemorySize,
                             QKV_SMEM_HALFS * (int)sizeof(__half));
        smem_set = 1;
    }

    prep_kernel<<<(X2_TOTAL + W2_TOTAL + 255)/256, 256>>>(x, Wq, Wk, Wv);
    qkv_mma_kernel<<<dim3(N_/128, B_), 256, QKV_SMEM_HALFS * sizeof(__half)>>>(bq, bk, bv);
    se_kernel<<<B_, 256>>>(x, se_w1, se_w2);
    attn_kernel<<<dim3(N_/BM, B_), 256, SMEM_HALFS * sizeof(__half)>>>(x, gamma, out);
}